// round 7
// baseline (speedup 1.0000x reference)
#include <cuda_runtime.h>
#include <cuda_fp16.h>
#include <stdint.h>
#include <math.h>

#define Bsz 4
#define Tsz 2048
#define Dsz 1024
#define BT  (Bsz * Tsz)

typedef __half h16;

// ---------------- scratch (__device__ globals; allocation-free rule) -------
__device__ __align__(16) h16 g_s[(size_t)Bsz * Tsz * Tsz];   // fp16 scores
__device__ __align__(16) h16 g_xf[(size_t)BT * Dsz];
__device__ __align__(16) h16 g_wf[3][(size_t)Dsz * Dsz];     // [3072,1024]
__device__ __align__(16) h16 g_qkv[(size_t)BT * 3 * Dsz];    // [8192, 3072]
__device__ __align__(16) h16 g_pf[(size_t)Bsz * Tsz * Tsz];

// ---------------- low-level helpers (plain sm_80-era PTX only) --------------
__device__ __forceinline__ uint32_t smem_u32(const void* p) {
    uint32_t a;
    asm("{ .reg .u64 t; cvta.to.shared.u64 t, %1; cvt.u32.u64 %0, t; }"
        : "=r"(a) : "l"(p));
    return a;
}

#define CP_ASYNC16(dst, src) \
    asm volatile("cp.async.cg.shared.global [%0], [%1], 16;" \
                 :: "r"(dst), "l"(src))
#define CP_COMMIT() asm volatile("cp.async.commit_group;")
#define CP_WAIT1()  asm volatile("cp.async.wait_group 1;")

__device__ __forceinline__ void ldsm4(uint32_t& r0, uint32_t& r1,
                                      uint32_t& r2, uint32_t& r3,
                                      uint32_t addr) {
    asm volatile("ldmatrix.sync.aligned.m8n8.x4.shared.b16 {%0,%1,%2,%3}, [%4];"
                 : "=r"(r0), "=r"(r1), "=r"(r2), "=r"(r3) : "r"(addr));
}

__device__ __forceinline__ void ldsm4t(uint32_t& r0, uint32_t& r1,
                                       uint32_t& r2, uint32_t& r3,
                                       uint32_t addr) {
    asm volatile(
        "ldmatrix.sync.aligned.m8n8.x4.trans.shared.b16 {%0,%1,%2,%3}, [%4];"
        : "=r"(r0), "=r"(r1), "=r"(r2), "=r"(r3) : "r"(addr));
}

__device__ __forceinline__ void mma16816(float* d, const uint32_t* a,
                                         const uint32_t* b) {
    asm volatile(
        "mma.sync.aligned.m16n8k16.row.col.f32.f16.f16.f32 "
        "{%0,%1,%2,%3}, {%4,%5,%6,%7}, {%8,%9}, {%0,%1,%2,%3};"
        : "+f"(d[0]), "+f"(d[1]), "+f"(d[2]), "+f"(d[3])
        : "r"(a[0]), "r"(a[1]), "r"(a[2]), "r"(a[3]), "r"(b[0]), "r"(b[1]));
}

// ---------------- HMMA GEMM ---------------------------------------------------
// C[M,N] = A[M,K] * op(B).  bnn=0: B is [N,K] (NT).  bnn=1: B is [K,N] (NN).
// fp16 operands, fp32 accumulate. lda/ldb/ldc row strides (elements).
// mode 0: full grid.
// mode 1: blockIdx.x is a linear lower-triangular tile index (S-GEMM).
// mode 2: kend = row0+128, heavy rows first (PV GEMM).
// ofp16: write C as fp16 (else fp32).
#define KC     64
#define ROWB   144               // NT tile: 128B data + 16B pad per row
#define ROWBB  272               // NN B tile: 256B data + 16B pad per k-row
#define MATB   (128 * ROWB)      // 18432 B
#define STGB   (2 * MATB)        // A tile + B tile (NN B: 64*272=17408 <= MATB)
#define NSTG   3
#define SMEMB  (NSTG * STGB)     // 110592 B

__global__ void __launch_bounds__(256, 2) hgemm(
    const h16* __restrict__ Af, const h16* __restrict__ Bf,
    void* __restrict__ Cv, int K, int lda, int ldb, int ldc,
    int mode, int ofp16, int bnn, long long sA, long long sB, long long sC)
{
    const int bz = blockIdx.z;
    Af += (size_t)bz * sA;
    Bf += (size_t)bz * sB;

    int row0, col0;
    if (mode == 1) {
        // triangular decode: t -> (r, c), r >= c
        const int t = blockIdx.x;
        int r = (int)((__fsqrt_rn(8.f * (float)t + 1.f) - 1.f) * 0.5f);
        while ((r + 1) * (r + 2) / 2 <= t) r++;
        while (r * (r + 1) / 2 > t) r--;
        row0 = r * 128;
        col0 = (t - r * (r + 1) / 2) * 128;
    } else if (mode == 2) {
        const int by = (int)gridDim.y - 1 - (int)blockIdx.y;  // heavy first
        row0 = by * 128;
        col0 = blockIdx.x * 128;
    } else {
        row0 = blockIdx.y * 128;
        col0 = blockIdx.x * 128;
    }
    const int kend = (mode == 2) ? (row0 + 128) : K;
    const int nc = kend / KC;           // >= 2 always

    extern __shared__ char smc[];
    const uint32_t smb = smem_u32(smc);
    const int tid  = threadIdx.x;
    const int lane = tid & 31;
    const int wid  = tid >> 5;
    const int m0 = (wid & 1) * 64;      // warp tile 64x32, warps 2x4
    const int n0 = (wid >> 1) * 32;

    float acc[4][4][4];
#pragma unroll
    for (int i = 0; i < 4; i++)
#pragma unroll
        for (int j = 0; j < 4; j++)
#pragma unroll
            for (int q = 0; q < 4; q++) acc[i][j][q] = 0.f;

    const int lch  = tid & 7;      // NT: 16B chunk within 128B row
    const int lr0  = tid >> 3;     // 0..31
    const int lch2 = tid & 15;     // NN B: 16B chunk within 256B row
    const int lr2  = tid >> 4;     // 0..15

    auto do_load = [&](int st, int k0) {
        const uint32_t sb = smb + (uint32_t)st * STGB;
        const h16* pA = Af + (size_t)row0 * lda + k0;
#pragma unroll
        for (int j = 0; j < 4; j++) {
            const int row = lr0 + j * 32;
            CP_ASYNC16(sb + (uint32_t)(row * ROWB + lch * 16),
                       pA + (size_t)row * lda + lch * 8);
        }
        if (!bnn) {
            const h16* pB = Bf + (size_t)col0 * ldb + k0;
#pragma unroll
            for (int j = 0; j < 4; j++) {
                const int row = lr0 + j * 32;
                CP_ASYNC16(sb + MATB + (uint32_t)(row * ROWB + lch * 16),
                           pB + (size_t)row * ldb + lch * 8);
            }
        } else {
            const h16* pB = Bf + (size_t)k0 * ldb + col0;
#pragma unroll
            for (int j = 0; j < 4; j++) {
                const int row = lr2 + j * 16;     // k-row 0..63
                CP_ASYNC16(sb + MATB + (uint32_t)(row * ROWBB + lch2 * 16),
                           pB + (size_t)row * ldb + lch2 * 8);
            }
        }
    };

    do_load(0, 0);
    CP_COMMIT();
    do_load(1, KC);
    CP_COMMIT();

    for (int c = 0; c < nc; c++) {
        CP_WAIT1();                      // stage c resident
        __syncthreads();                 // all warps done with stage (c+2)%3
        if (c + 2 < nc) do_load((c + 2) % NSTG, (c + 2) * KC);
        CP_COMMIT();

        const uint32_t base = smb + (uint32_t)(c % NSTG) * STGB;
#pragma unroll
        for (int kk = 0; kk < 4; kk++) {          // four k16 steps per KC=64
            uint32_t a[4][4];
#pragma unroll
            for (int mi = 0; mi < 4; mi++) {
                const uint32_t ad = base +
                    (uint32_t)((m0 + mi * 16 + (lane & 15)) * ROWB +
                               (kk * 2 + (lane >> 4)) * 16);
                ldsm4(a[mi][0], a[mi][1], a[mi][2], a[mi][3], ad);
            }
            uint32_t bb[4][2];
            if (!bnn) {
#pragma unroll
                for (int np = 0; np < 2; np++) {  // [N,K]: non-trans ldsm
                    const int rb = n0 + np * 16 + (lane & 7) + ((lane >> 4) << 3);
                    const int ch = kk * 2 + ((lane >> 3) & 1);
                    const uint32_t ad = base + MATB +
                        (uint32_t)(rb * ROWB + ch * 16);
                    ldsm4(bb[np*2][0], bb[np*2][1],
                          bb[np*2+1][0], bb[np*2+1][1], ad);
                }
            } else {
#pragma unroll
                for (int g = 0; g < 2; g++) {     // [K,N]: trans ldsm
                    const uint32_t ad = base + MATB +
                        (uint32_t)((kk * 16 + (lane & 15)) * ROWBB +
                                   (n0 + g * 16 + ((lane >> 4) << 3)) * 2);
                    ldsm4t(bb[g*2][0], bb[g*2][1],
                           bb[g*2+1][0], bb[g*2+1][1], ad);
                }
            }
#pragma unroll
            for (int mi = 0; mi < 4; mi++)
#pragma unroll
                for (int ni = 0; ni < 4; ni++)
                    mma16816(acc[mi][ni], a[mi], bb[ni]);
        }
    }

    // epilogue
    const int er = lane >> 2;
    const int ec = (lane & 3) * 2;
    if (!ofp16) {
        float* C = (float*)Cv + (size_t)bz * sC;
#pragma unroll
        for (int mi = 0; mi < 4; mi++) {
            const int r = row0 + m0 + mi * 16 + er;
#pragma unroll
            for (int ni = 0; ni < 4; ni++) {
                const int cc = col0 + n0 + ni * 8 + ec;
                *(float2*)&C[(size_t)r * ldc + cc] =
                    make_float2(acc[mi][ni][0], acc[mi][ni][1]);
                *(float2*)&C[(size_t)(r + 8) * ldc + cc] =
                    make_float2(acc[mi][ni][2], acc[mi][ni][3]);
            }
        }
    } else {
        h16* C = (h16*)Cv + (size_t)bz * sC;
#pragma unroll
        for (int mi = 0; mi < 4; mi++) {
            const int r = row0 + m0 + mi * 16 + er;
#pragma unroll
            for (int ni = 0; ni < 4; ni++) {
                const int cc = col0 + n0 + ni * 8 + ec;
                __half2 h0 = __floats2half2_rn(acc[mi][ni][0], acc[mi][ni][1]);
                __half2 h1 = __floats2half2_rn(acc[mi][ni][2], acc[mi][ni][3]);
                *(__half2*)&C[(size_t)r * ldc + cc] = h0;
                *(__half2*)&C[(size_t)(r + 8) * ldc + cc] = h1;
            }
        }
    }
}

// ---------------- conversions ------------------------------------------------
__global__ void __launch_bounds__(256) conv_single(
    const float* __restrict__ in, h16* __restrict__ o, int n4)
{
    int i = blockIdx.x * 256 + threadIdx.x;
    if (i >= n4) return;
    float4 v = ((const float4*)in)[i];
    __half2 p0 = __floats2half2_rn(v.x, v.y);
    __half2 p1 = __floats2half2_rn(v.z, v.w);
    uint2 u;
    u.x = *(uint32_t*)&p0;
    u.y = *(uint32_t*)&p1;
    ((uint2*)o)[i] = u;
}

__global__ void __launch_bounds__(256) conv_w3(
    const float* __restrict__ w0, const float* __restrict__ w1,
    const float* __restrict__ w2, h16* __restrict__ o, int n4each)
{
    int i = blockIdx.x * 256 + threadIdx.x;
    if (i >= 3 * n4each) return;
    const int m = i / n4each;
    const int r = i - m * n4each;
    const float* in = (m == 0) ? w0 : (m == 1) ? w1 : w2;
    float4 v = ((const float4*)in)[r];
    __half2 p0 = __floats2half2_rn(v.x, v.y);
    __half2 p1 = __floats2half2_rn(v.z, v.w);
    uint2 u;
    u.x = *(uint32_t*)&p0;
    u.y = *(uint32_t*)&p1;
    ((uint2*)o)[i] = u;
}

// ---------------- causal softmax over fp16 S -> fp16 P ----------------------
__device__ __forceinline__ float warp_max_f(float v) {
#pragma unroll
    for (int o = 16; o; o >>= 1) v = fmaxf(v, __shfl_xor_sync(0xffffffffu, v, o));
    return v;
}
__device__ __forceinline__ float warp_sum_f(float v) {
#pragma unroll
    for (int o = 16; o; o >>= 1) v += __shfl_xor_sync(0xffffffffu, v, o);
    return v;
}

__global__ void __launch_bounds__(256) softmax_pf(
    const h16* __restrict__ S, h16* __restrict__ pf)
{
    __shared__ float es[Tsz];
    __shared__ float red[8];
    const int b = blockIdx.y;
    const int r = blockIdx.x;
    const h16* row = S + ((size_t)b * Tsz + r) * Tsz;
    h16* pr = pf + ((size_t)b * Tsz + r) * Tsz;
    const int blk_end = ((r >> 7) + 1) << 7;   // padded to 128
    const int n8 = blk_end >> 3;
    const float scale = 0.03125f;              // 1/sqrt(1024)
    const int tid = threadIdx.x;

    // pass 1: masked max (8 halves per load)
    float m = -INFINITY;
    for (int i8 = tid; i8 < n8; i8 += 256) {
        uint4 u = ((const uint4*)row)[i8];
        float2 f0 = __half22float2(*(__half2*)&u.x);
        float2 f1 = __half22float2(*(__half2*)&u.y);
        float2 f2 = __half22float2(*(__half2*)&u.z);
        float2 f3 = __half22float2(*(__half2*)&u.w);
        const int base = i8 << 3;
        if (base + 7 <= r) {
            m = fmaxf(m, fmaxf(fmaxf(f0.x, f0.y), fmaxf(f1.x, f1.y)));
            m = fmaxf(m, fmaxf(fmaxf(f2.x, f2.y), fmaxf(f3.x, f3.y)));
        } else {
            float vv[8] = {f0.x, f0.y, f1.x, f1.y, f2.x, f2.y, f3.x, f3.y};
#pragma unroll
            for (int j = 0; j < 8; j++)
                if (base + j <= r) m = fmaxf(m, vv[j]);
        }
    }
    m = warp_max_f(m);
    if ((tid & 31) == 0) red[tid >> 5] = m;
    __syncthreads();
    m = red[0];
#pragma unroll
    for (int i = 1; i < 8; i++) m = fmaxf(m, red[i]);
    __syncthreads();

    // pass 2: masked exp + sum (masked lanes contribute exact 0)
    float ssum = 0.f;
    for (int i8 = tid; i8 < n8; i8 += 256) {
        uint4 u = ((const uint4*)row)[i8];
        float2 f0 = __half22float2(*(__half2*)&u.x);
        float2 f1 = __half22float2(*(__half2*)&u.y);
        float2 f2 = __half22float2(*(__half2*)&u.z);
        float2 f3 = __half22float2(*(__half2*)&u.w);
        float vv[8] = {f0.x, f0.y, f1.x, f1.y, f2.x, f2.y, f3.x, f3.y};
        const int base = i8 << 3;
        float e[8];
#pragma unroll
        for (int j = 0; j < 8; j++) {
            e[j] = (base + j <= r) ? __expf((vv[j] - m) * scale) : 0.f;
            ssum += e[j];
        }
        ((float4*)es)[i8 * 2 + 0] = make_float4(e[0], e[1], e[2], e[3]);
        ((float4*)es)[i8 * 2 + 1] = make_float4(e[4], e[5], e[6], e[7]);
    }
    ssum = warp_sum_f(ssum);
    if ((tid & 31) == 0) red[tid >> 5] = ssum;
    __syncthreads();
    ssum = 0.f;
#pragma unroll
    for (int i = 0; i < 8; i++) ssum += red[i];
    const float inv = 1.f / ssum;
    __syncthreads();

    // pass 3: normalize + write fp16 (tail zeros come for free)
    for (int i8 = tid; i8 < n8; i8 += 256) {
        float4 e0 = ((const float4*)es)[i8 * 2 + 0];
        float4 e1 = ((const float4*)es)[i8 * 2 + 1];
        __half2 h0 = __floats2half2_rn(e0.x * inv, e0.y * inv);
        __half2 h1 = __floats2half2_rn(e0.z * inv, e0.w * inv);
        __half2 h2 = __floats2half2_rn(e1.x * inv, e1.y * inv);
        __half2 h3 = __floats2half2_rn(e1.z * inv, e1.w * inv);
        uint4 u;
        u.x = *(uint32_t*)&h0;
        u.y = *(uint32_t*)&h1;
        u.z = *(uint32_t*)&h2;
        u.w = *(uint32_t*)&h3;
        ((uint4*)pr)[i8] = u;
    }
}

// ---------------- launch ------------------------------------------------------
extern "C" void kernel_launch(void* const* d_in, const int* in_sizes, int n_in,
                              void* d_out, int out_size)
{
    (void)in_sizes; (void)n_in; (void)out_size;
    const float* x = (const float*)d_in[0];
    float* out = (float*)d_out;

    h16 *s, *xf, *wf, *qkv, *pf;
    cudaGetSymbolAddress((void**)&s,   g_s);
    cudaGetSymbolAddress((void**)&xf,  g_xf);
    cudaGetSymbolAddress((void**)&wf,  g_wf);
    cudaGetSymbolAddress((void**)&qkv, g_qkv);
    cudaGetSymbolAddress((void**)&pf,  g_pf);

    cudaFuncSetAttribute(hgemm, cudaFuncAttributeMaxDynamicSharedMemorySize,
                         SMEMB);

    const int nX = BT * Dsz;    // 8M
    const int nW = Dsz * Dsz;   // 1M

    conv_single<<<nX / 4 / 256, 256>>>(x, xf, nX / 4);
    conv_w3<<<3 * (nW / 4) / 256, 256>>>((const float*)d_in[1],
                                         (const float*)d_in[2],
                                         (const float*)d_in[3], wf, nW / 4);

    // fused QKV projection: [8192, 3072] = x @ [Wq;Wk;Wv]^T, fp16 out (NT)
    hgemm<<<dim3(3 * Dsz / 128, BT / 128, 1), 256, SMEMB>>>(
        xf, wf, qkv, Dsz, Dsz, Dsz, 3 * Dsz, 0, 1, 0, 0, 0, 0);

    const h16* qf = qkv;
    const h16* kf = qkv + Dsz;
    const h16* vf = qkv + 2 * Dsz;

    // S = Q @ K^T (NT, exact lower-triangular tile grid, fp16 out)
    const int ntiles = (Tsz / 128) * (Tsz / 128 + 1) / 2;   // 136
    hgemm<<<dim3(ntiles, 1, Bsz), 256, SMEMB>>>(
        qf, kf, s, Dsz, 3 * Dsz, 3 * Dsz, Tsz, 1, 1, 0,
        (long long)Tsz * 3 * Dsz, (long long)Tsz * 3 * Dsz,
        (long long)Tsz * Tsz);

    // causal softmax (fp16 S) -> P fp16 (tail zero-filled to 128 boundary)
    softmax_pf<<<dim3(Tsz, Bsz), 256>>>(s, pf);

    // O = P @ V (NN: V read in place from qkv, K clipped to row0+128)
    hgemm<<<dim3(Dsz / 128, Tsz / 128, Bsz), 256, SMEMB>>>(
        pf, vf, out, Tsz, Tsz, 3 * Dsz, Dsz, 2, 0, 1,
        (long long)Tsz * Tsz, (long long)Tsz * 3 * Dsz,
        (long long)Tsz * Dsz);
}